// round 1
// baseline (speedup 1.0000x reference)
#include <cuda_runtime.h>

// LGCN layer: out = D_in^{-1/2} * A * D_out^{-1/2} * x
// x: [N, 96] f32, src/dst: [E] int64-or-int32 (detected on device), out: [N, 96] f32.

#define DFEAT   96
#define DV      24        // float4 chunks per row
#define MAXN    50000

__device__ int   g_outdeg[MAXN];
__device__ int   g_indeg[MAXN];
__device__ float g_rsout[MAXN];
__device__ float g_rsin[MAXN];
__device__ int   g_is64;

__device__ __forceinline__ int load_idx(const void* p, int e, int is64) {
    if (is64) return (int)((const long long*)p)[e];
    return ((const int*)p)[e];
}

__device__ __forceinline__ void red_add_f4(float4* addr, float4 v) {
    asm volatile("red.global.add.v4.f32 [%0], {%1,%2,%3,%4};"
                 :: "l"(addr), "f"(v.x), "f"(v.y), "f"(v.z), "f"(v.w)
                 : "memory");
}

// K0: zero output + degree arrays, detect index width.
__global__ void k_init(float4* __restrict__ out, int n_nodes,
                       const unsigned long long* __restrict__ src_raw, int n_edges) {
    int i = blockIdx.x * blockDim.x + threadIdx.x;
    int nv = n_nodes * DV;
    if (i < nv) out[i] = make_float4(0.f, 0.f, 0.f, 0.f);
    if (i < n_nodes) { g_outdeg[i] = 0; g_indeg[i] = 0; }
    if (i == 0) {
        // If data is really int32, a u64 view packs two random indices; the
        // high half is nonzero w.p. ~1, making the value >= n_nodes.
        int is64 = 1;
        int k = n_edges < 64 ? n_edges : 64;
        for (int j = 0; j < k; j++) {
            if (src_raw[j] >= (unsigned long long)n_nodes) { is64 = 0; break; }
        }
        g_is64 = is64;
    }
}

// K1: degree histograms.
__global__ void k_deg(const void* __restrict__ src, const void* __restrict__ dst,
                      int n_edges) {
    int e = blockIdx.x * blockDim.x + threadIdx.x;
    if (e >= n_edges) return;
    int is64 = g_is64;
    int s = load_idx(src, e, is64);
    int d = load_idx(dst, e, is64);
    atomicAdd(&g_outdeg[s], 1);
    atomicAdd(&g_indeg[d], 1);
}

// K2: deg^{-1/2} with clip at 1.
__global__ void k_rs(int n_nodes) {
    int i = blockIdx.x * blockDim.x + threadIdx.x;
    if (i >= n_nodes) return;
    int od = g_outdeg[i]; if (od < 1) od = 1;
    int id = g_indeg[i];  if (id < 1) id = 1;
    g_rsout[i] = rsqrtf((float)od);
    g_rsin[i]  = rsqrtf((float)id);
}

// K3: edge scatter. One thread per (edge, float4-chunk): 24 chunks/edge.
__global__ void k_scatter(const float4* __restrict__ x,
                          const void* __restrict__ src, const void* __restrict__ dst,
                          float4* __restrict__ out, int n_edges) {
    long long i   = (long long)blockIdx.x * blockDim.x + threadIdx.x;
    long long tot = (long long)n_edges * DV;
    if (i >= tot) return;
    int e = (int)(i / DV);
    int c = (int)(i - (long long)e * DV);
    int is64 = g_is64;
    int s = load_idx(src, e, is64);
    int d = load_idx(dst, e, is64);
    float sc = g_rsout[s];
    float4 v = x[(long long)s * DV + c];
    v.x *= sc; v.y *= sc; v.z *= sc; v.w *= sc;
    red_add_f4(out + (long long)d * DV + c, v);
}

// K4: post-scale rows by in-degree^{-1/2}.
__global__ void k_final(float4* __restrict__ out, int n_nodes) {
    int i = blockIdx.x * blockDim.x + threadIdx.x;
    int nv = n_nodes * DV;
    if (i >= nv) return;
    int row = i / DV;
    float sc = g_rsin[row];
    float4 v = out[i];
    v.x *= sc; v.y *= sc; v.z *= sc; v.w *= sc;
    out[i] = v;
}

extern "C" void kernel_launch(void* const* d_in, const int* in_sizes, int n_in,
                              void* d_out, int out_size) {
    const float* x   = (const float*)d_in[0];
    const void*  src = d_in[1];
    const void*  dst = d_in[2];
    float* out = (float*)d_out;

    int n_nodes = in_sizes[0] / DFEAT;   // 50000
    int n_edges = in_sizes[1];           // 800000

    const int B = 256;
    int nv = n_nodes * DV;               // 1.2M float4 elements in out

    k_init<<<(nv + B - 1) / B, B>>>((float4*)out, n_nodes,
                                    (const unsigned long long*)src, n_edges);
    k_deg<<<(n_edges + B - 1) / B, B>>>(src, dst, n_edges);
    k_rs<<<(n_nodes + B - 1) / B, B>>>(n_nodes);
    long long tot = (long long)n_edges * DV;
    k_scatter<<<(int)((tot + B - 1) / B), B>>>((const float4*)x, src, dst,
                                               (float4*)out, n_edges);
    k_final<<<(nv + B - 1) / B, B>>>((float4*)out, n_nodes);
}

// round 2
// speedup vs baseline: 1.3134x; 1.3134x over previous
#include <cuda_runtime.h>

// LGCN layer: out = D_in^{-1/2} * A * D_out^{-1/2} * x
// Round 2: device-built dst-CSR + warp-per-node gather (no feature atomics).

#define DFEAT   96
#define DV      24          // float4 chunks per row
#define MAXN    50048
#define MAXE    800000
#define CHUNK   1024        // scan chunk
#define MAXBLK  256

__device__ int   g_outdeg[MAXN];
__device__ int   g_indeg[MAXN];
__device__ float g_rsout[MAXN];
__device__ int   g_rowstart[MAXN + 1];
__device__ int   g_cursor[MAXN];
__device__ int   g_csr[MAXE];
__device__ int   g_blocksum[MAXBLK];
__device__ int   g_blockoff[MAXBLK];
__device__ int   g_is64;

__device__ __forceinline__ int load_idx(const void* p, int e, int is64) {
    if (is64) return (int)((const long long*)p)[e];
    return ((const int*)p)[e];
}

// K0: zero degrees + detect index width.
__global__ void k_init(int n_nodes, const unsigned long long* __restrict__ src_raw,
                       int n_edges) {
    int i = blockIdx.x * blockDim.x + threadIdx.x;
    if (i < n_nodes) { g_outdeg[i] = 0; g_indeg[i] = 0; }
    if (i == 0) {
        // int32 data viewed as u64 packs two random indices -> huge w.p. ~1.
        int is64 = 1;
        int k = n_edges < 64 ? n_edges : 64;
        for (int j = 0; j < k; j++)
            if (src_raw[j] >= (unsigned long long)n_nodes) { is64 = 0; break; }
        g_is64 = is64;
    }
}

// K1: degree histograms.
__global__ void k_deg(const void* __restrict__ src, const void* __restrict__ dst,
                      int n_edges) {
    int e = blockIdx.x * blockDim.x + threadIdx.x;
    if (e >= n_edges) return;
    int is64 = g_is64;
    atomicAdd(&g_outdeg[load_idx(src, e, is64)], 1);
    atomicAdd(&g_indeg[load_idx(dst, e, is64)], 1);
}

// K2: out-degree^{-1/2} (clipped at 1). rsin folded into gather.
__global__ void k_rs(int n_nodes) {
    int i = blockIdx.x * blockDim.x + threadIdx.x;
    if (i >= n_nodes) return;
    int od = g_outdeg[i]; if (od < 1) od = 1;
    g_rsout[i] = rsqrtf((float)od);
}

// K3a: per-chunk sums of indeg.
__global__ void k_scan_sum(int n) {
    __shared__ int sd[CHUNK];
    int i = blockIdx.x * CHUNK + threadIdx.x;
    sd[threadIdx.x] = (i < n) ? g_indeg[i] : 0;
    __syncthreads();
    for (int s = CHUNK / 2; s > 0; s >>= 1) {
        if (threadIdx.x < s) sd[threadIdx.x] += sd[threadIdx.x + s];
        __syncthreads();
    }
    if (threadIdx.x == 0) g_blocksum[blockIdx.x] = sd[0];
}

// K3b: exclusive scan of chunk sums (nblk <= 256).
__global__ void k_scan_top(int nblk) {
    __shared__ int s[MAXBLK];
    int t = threadIdx.x;
    if (t < nblk) s[t] = g_blocksum[t];
    __syncthreads();
    if (t == 0) {
        int acc = 0;
        for (int b = 0; b < nblk; b++) { int v = s[b]; s[b] = acc; acc += v; }
    }
    __syncthreads();
    if (t < nblk) g_blockoff[t] = s[t];
}

// K3c: block-wide exclusive scan + chunk offset -> row_start, cursor.
__global__ void k_scan_final(int n) {
    __shared__ int warpsum[32];
    int i = blockIdx.x * CHUNK + threadIdx.x;
    int v = (i < n) ? g_indeg[i] : 0;
    int lane = threadIdx.x & 31, wid = threadIdx.x >> 5;
    int inc = v;
    #pragma unroll
    for (int o = 1; o < 32; o <<= 1) {
        int t = __shfl_up_sync(0xFFFFFFFFu, inc, o);
        if (lane >= o) inc += t;
    }
    if (lane == 31) warpsum[wid] = inc;
    __syncthreads();
    if (wid == 0) {
        int orig = warpsum[lane];
        int sc = orig;
        #pragma unroll
        for (int o = 1; o < 32; o <<= 1) {
            int t = __shfl_up_sync(0xFFFFFFFFu, sc, o);
            if (lane >= o) sc += t;
        }
        warpsum[lane] = sc - orig;   // exclusive per-warp offset
    }
    __syncthreads();
    int excl = inc - v + warpsum[wid] + g_blockoff[blockIdx.x];
    if (i < n) { g_rowstart[i] = excl; g_cursor[i] = excl; }
    if (i == n - 1) g_rowstart[n] = excl + v;
}

// K4: scatter edge srcs into CSR buckets by dst.
__global__ void k_fill(const void* __restrict__ src, const void* __restrict__ dst,
                       int n_edges) {
    int e = blockIdx.x * blockDim.x + threadIdx.x;
    if (e >= n_edges) return;
    int is64 = g_is64;
    int s = load_idx(src, e, is64);
    int d = load_idx(dst, e, is64);
    int pos = atomicAdd(&g_cursor[d], 1);
    g_csr[pos] = s;
}

// K5: warp-per-node gather. Lanes 0..23 hold the 24 float4 chunks in regs.
__global__ void k_gather(const float4* __restrict__ x, float4* __restrict__ out,
                         int n_nodes) {
    int w = (blockIdx.x * blockDim.x + threadIdx.x) >> 5;
    if (w >= n_nodes) return;
    int lane = threadIdx.x & 31;
    int beg = g_rowstart[w];
    int end = g_rowstart[w + 1];
    float4 acc = make_float4(0.f, 0.f, 0.f, 0.f);
    for (int j = beg; j < end; j++) {
        int s = g_csr[j];          // warp-uniform broadcast
        float sc = g_rsout[s];     // warp-uniform broadcast
        if (lane < DV) {
            float4 v = x[s * DV + lane];
            acc.x = fmaf(v.x, sc, acc.x);
            acc.y = fmaf(v.y, sc, acc.y);
            acc.z = fmaf(v.z, sc, acc.z);
            acc.w = fmaf(v.w, sc, acc.w);
        }
    }
    int deg = end - beg; if (deg < 1) deg = 1;
    float rsin = rsqrtf((float)deg);
    if (lane < DV) {
        acc.x *= rsin; acc.y *= rsin; acc.z *= rsin; acc.w *= rsin;
        out[w * DV + lane] = acc;
    }
}

extern "C" void kernel_launch(void* const* d_in, const int* in_sizes, int n_in,
                              void* d_out, int out_size) {
    const float* x   = (const float*)d_in[0];
    const void*  src = d_in[1];
    const void*  dst = d_in[2];
    float* out = (float*)d_out;

    int n_nodes = in_sizes[0] / DFEAT;   // 50000
    int n_edges = in_sizes[1];           // 800000

    const int B = 256;
    int nblk_scan = (n_nodes + CHUNK - 1) / CHUNK;

    k_init<<<(n_nodes + B - 1) / B, B>>>(n_nodes,
                                         (const unsigned long long*)src, n_edges);
    k_deg<<<(n_edges + B - 1) / B, B>>>(src, dst, n_edges);
    k_rs<<<(n_nodes + B - 1) / B, B>>>(n_nodes);
    k_scan_sum<<<nblk_scan, CHUNK>>>(n_nodes);
    k_scan_top<<<1, MAXBLK>>>(nblk_scan);
    k_scan_final<<<nblk_scan, CHUNK>>>(n_nodes);
    k_fill<<<(n_edges + B - 1) / B, B>>>(src, dst, n_edges);
    int gather_threads = n_nodes * 32;
    k_gather<<<(gather_threads + B - 1) / B, B>>>((const float4*)x,
                                                  (float4*)out, n_nodes);
}

// round 3
// speedup vs baseline: 1.4439x; 1.0994x over previous
#include <cuda_runtime.h>

// LGCN layer: out = D_in^{-1/2} * A * D_out^{-1/2} * x
// Round 3: slim aux pipeline (6 launches), fast scan, pipelined gather.

#define DFEAT   96
#define DV      24          // float4 chunks per row
#define MAXN    50048
#define MAXE    800000
#define CHUNK   1024        // scan chunk (elements)
#define MAXBLK  256

__device__ int   g_outdeg[MAXN];
__device__ int   g_indeg[MAXN];
__device__ float g_rsout[MAXN];
__device__ int   g_rowstart[MAXN + 1];
__device__ int   g_cursor[MAXN];
__device__ int   g_csr[MAXE];
__device__ int   g_blocksum[MAXBLK];
__device__ int   g_is64;

__device__ __forceinline__ int load_idx(const void* p, int e, int is64) {
    if (is64) return (int)((const long long*)p)[e];
    return ((const int*)p)[e];
}

// K0: zero degrees + detect index width.
__global__ void k_init(int n_nodes, const unsigned long long* __restrict__ src_raw,
                       int n_edges) {
    int i = blockIdx.x * blockDim.x + threadIdx.x;
    if (i < n_nodes) { g_outdeg[i] = 0; g_indeg[i] = 0; }
    if (i == 0) {
        // int32 data viewed as u64 packs two random indices -> huge w.p. ~1.
        int is64 = 1;
        int k = n_edges < 64 ? n_edges : 64;
        for (int j = 0; j < k; j++)
            if (src_raw[j] >= (unsigned long long)n_nodes) { is64 = 0; break; }
        g_is64 = is64;
    }
}

// K1: degree histograms.
__global__ void k_deg(const void* __restrict__ src, const void* __restrict__ dst,
                      int n_edges) {
    int e = blockIdx.x * blockDim.x + threadIdx.x;
    if (e >= n_edges) return;
    int is64 = g_is64;
    atomicAdd(&g_outdeg[load_idx(src, e, is64)], 1);
    atomicAdd(&g_indeg[load_idx(dst, e, is64)], 1);
}

// K2: per-chunk sums of indeg. 256 threads, int4 loads, shfl reduce.
__global__ void k_scan_sum(int n) {
    __shared__ int wsum[8];
    int t = threadIdx.x;
    int base4 = blockIdx.x * (CHUNK / 4) + t;      // int4 index
    int v = 0;
    int e0 = base4 * 4;
    if (e0 + 3 < n) {
        int4 q = ((const int4*)g_indeg)[base4];
        v = q.x + q.y + q.z + q.w;
    } else {
        for (int k = 0; k < 4; k++)
            if (e0 + k < n) v += g_indeg[e0 + k];
    }
    #pragma unroll
    for (int o = 16; o > 0; o >>= 1) v += __shfl_down_sync(0xFFFFFFFFu, v, o);
    if ((t & 31) == 0) wsum[t >> 5] = v;
    __syncthreads();
    if (t == 0) {
        int s = 0;
        #pragma unroll
        for (int w = 0; w < 8; w++) s += wsum[w];
        g_blocksum[blockIdx.x] = s;
    }
}

// K3: block exclusive scan + in-kernel blocksum prefix + rowstart/cursor/rsout.
__global__ void k_scan_final(int n, int nblk) {
    __shared__ int warpsum[32];
    __shared__ int blockoff;
    int i = blockIdx.x * CHUNK + threadIdx.x;
    int v = (i < n) ? g_indeg[i] : 0;
    int lane = threadIdx.x & 31, wid = threadIdx.x >> 5;

    // thread 0 computes this block's global offset (nblk <= 64: trivial serial).
    if (threadIdx.x == 0) {
        int acc = 0;
        for (int b = 0; b < blockIdx.x; b++) acc += g_blocksum[b];
        blockoff = acc;
    }

    int inc = v;
    #pragma unroll
    for (int o = 1; o < 32; o <<= 1) {
        int t = __shfl_up_sync(0xFFFFFFFFu, inc, o);
        if (lane >= o) inc += t;
    }
    if (lane == 31) warpsum[wid] = inc;
    __syncthreads();
    if (wid == 0) {
        int orig = warpsum[lane];
        int sc = orig;
        #pragma unroll
        for (int o = 1; o < 32; o <<= 1) {
            int t = __shfl_up_sync(0xFFFFFFFFu, sc, o);
            if (lane >= o) sc += t;
        }
        warpsum[lane] = sc - orig;   // exclusive per-warp offset
    }
    __syncthreads();
    int excl = inc - v + warpsum[wid] + blockoff;
    if (i < n) {
        g_rowstart[i] = excl;
        g_cursor[i]   = excl;
        int od = g_outdeg[i]; if (od < 1) od = 1;
        g_rsout[i] = rsqrtf((float)od);
    }
    if (i == n - 1) g_rowstart[n] = excl + v;
}

// K4: scatter edge srcs into CSR buckets by dst.
__global__ void k_fill(const void* __restrict__ src, const void* __restrict__ dst,
                       int n_edges) {
    int e = blockIdx.x * blockDim.x + threadIdx.x;
    if (e >= n_edges) return;
    int is64 = g_is64;
    int s = load_idx(src, e, is64);
    int d = load_idx(dst, e, is64);
    int pos = atomicAdd(&g_cursor[d], 1);
    g_csr[pos] = s;
}

// K5: warp-per-node gather, software-pipelined index load.
__global__ void __launch_bounds__(256) k_gather(const float4* __restrict__ x,
                                                float4* __restrict__ out,
                                                int n_nodes) {
    int w = (blockIdx.x * blockDim.x + threadIdx.x) >> 5;
    if (w >= n_nodes) return;
    int lane = threadIdx.x & 31;
    int beg = g_rowstart[w];
    int end = g_rowstart[w + 1];
    float4 acc = make_float4(0.f, 0.f, 0.f, 0.f);
    int sNext = (beg < end) ? g_csr[beg] : 0;
    for (int j = beg; j < end; j++) {
        int s = sNext;
        if (j + 1 < end) sNext = g_csr[j + 1];   // prefetch next index
        float sc = g_rsout[s];                   // warp-uniform broadcast
        if (lane < DV) {
            float4 v = x[s * DV + lane];
            acc.x = fmaf(v.x, sc, acc.x);
            acc.y = fmaf(v.y, sc, acc.y);
            acc.z = fmaf(v.z, sc, acc.z);
            acc.w = fmaf(v.w, sc, acc.w);
        }
    }
    int deg = end - beg; if (deg < 1) deg = 1;
    float rsin = rsqrtf((float)deg);
    if (lane < DV) {
        acc.x *= rsin; acc.y *= rsin; acc.z *= rsin; acc.w *= rsin;
        out[w * DV + lane] = acc;
    }
}

extern "C" void kernel_launch(void* const* d_in, const int* in_sizes, int n_in,
                              void* d_out, int out_size) {
    const float* x   = (const float*)d_in[0];
    const void*  src = d_in[1];
    const void*  dst = d_in[2];
    float* out = (float*)d_out;

    int n_nodes = in_sizes[0] / DFEAT;   // 50000
    int n_edges = in_sizes[1];           // 800000

    const int B = 256;
    int nblk_scan = (n_nodes + CHUNK - 1) / CHUNK;   // 49

    k_init<<<(n_nodes + B - 1) / B, B>>>(n_nodes,
                                         (const unsigned long long*)src, n_edges);
    k_deg<<<(n_edges + B - 1) / B, B>>>(src, dst, n_edges);
    k_scan_sum<<<nblk_scan, 256>>>(n_nodes);
    k_scan_final<<<nblk_scan, CHUNK>>>(n_nodes, nblk_scan);
    k_fill<<<(n_edges + B - 1) / B, B>>>(src, dst, n_edges);
    int gather_threads = n_nodes * 32;
    k_gather<<<(gather_threads + B - 1) / B, B>>>((const float4*)x,
                                                  (float4*)out, n_nodes);
}

// round 4
// speedup vs baseline: 1.4548x; 1.0075x over previous
#include <cuda_runtime.h>

// LGCN layer: out = D_in^{-1/2} * A * D_out^{-1/2} * x
// Round 4: warp-parallel blockoff, 2-edge vectorized deg/fill, unrolled gather.

#define DFEAT   96
#define DV      24          // float4 chunks per row
#define MAXN    50048
#define MAXE    800000
#define CHUNK   1024        // scan chunk (elements)
#define MAXBLK  256

__device__ int   g_outdeg[MAXN];
__device__ int   g_indeg[MAXN];
__device__ float g_rsout[MAXN];
__device__ int   g_rowstart[MAXN + 1];
__device__ int   g_cursor[MAXN];
__device__ int   g_csr[MAXE];
__device__ int   g_blocksum[MAXBLK];
__device__ int   g_is64;

// K0: zero degrees + detect index width.
__global__ void k_init(int n_nodes, const unsigned long long* __restrict__ src_raw,
                       int n_edges) {
    int i = blockIdx.x * blockDim.x + threadIdx.x;
    if (i < n_nodes) { g_outdeg[i] = 0; g_indeg[i] = 0; }
    if (i == 0) {
        // int32 data viewed as u64 packs two random indices -> huge w.p. ~1.
        int is64 = 1;
        int k = n_edges < 64 ? n_edges : 64;
        for (int j = 0; j < k; j++)
            if (src_raw[j] >= (unsigned long long)n_nodes) { is64 = 0; break; }
        g_is64 = is64;
    }
}

// K1: degree histograms, 2 edges per thread with vector index loads.
__global__ void k_deg(const void* __restrict__ src, const void* __restrict__ dst,
                      int n_edges) {
    int t = blockIdx.x * blockDim.x + threadIdx.x;
    int e0 = t * 2;
    if (e0 >= n_edges) return;
    int is64 = g_is64;
    int s0, s1, d0, d1;
    bool two = (e0 + 1 < n_edges);
    if (is64) {
        if (two) {
            ulonglong2 sv = ((const ulonglong2*)src)[t];
            ulonglong2 dv = ((const ulonglong2*)dst)[t];
            s0 = (int)sv.x; s1 = (int)sv.y; d0 = (int)dv.x; d1 = (int)dv.y;
        } else {
            s0 = (int)((const long long*)src)[e0]; s1 = 0;
            d0 = (int)((const long long*)dst)[e0]; d1 = 0;
        }
    } else {
        if (two) {
            int2 sv = ((const int2*)src)[t];
            int2 dv = ((const int2*)dst)[t];
            s0 = sv.x; s1 = sv.y; d0 = dv.x; d1 = dv.y;
        } else {
            s0 = ((const int*)src)[e0]; s1 = 0;
            d0 = ((const int*)dst)[e0]; d1 = 0;
        }
    }
    atomicAdd(&g_outdeg[s0], 1);
    atomicAdd(&g_indeg[d0], 1);
    if (two) {
        atomicAdd(&g_outdeg[s1], 1);
        atomicAdd(&g_indeg[d1], 1);
    }
}

// K2: per-chunk sums of indeg. 256 threads, int4 loads, shfl reduce.
__global__ void k_scan_sum(int n) {
    __shared__ int wsum[8];
    int t = threadIdx.x;
    int base4 = blockIdx.x * (CHUNK / 4) + t;      // int4 index
    int v = 0;
    int e0 = base4 * 4;
    if (e0 + 3 < n) {
        int4 q = ((const int4*)g_indeg)[base4];
        v = q.x + q.y + q.z + q.w;
    } else {
        for (int k = 0; k < 4; k++)
            if (e0 + k < n) v += g_indeg[e0 + k];
    }
    #pragma unroll
    for (int o = 16; o > 0; o >>= 1) v += __shfl_down_sync(0xFFFFFFFFu, v, o);
    if ((t & 31) == 0) wsum[t >> 5] = v;
    __syncthreads();
    if (t == 0) {
        int s = 0;
        #pragma unroll
        for (int w = 0; w < 8; w++) s += wsum[w];
        g_blocksum[blockIdx.x] = s;
    }
}

// K3: block exclusive scan; warp-parallel blockoff; writes rowstart/cursor/rsout.
__global__ void k_scan_final(int n, int nblk) {
    __shared__ int warpsum[32];
    __shared__ int blockoff;
    int i = blockIdx.x * CHUNK + threadIdx.x;
    int v = (i < n) ? g_indeg[i] : 0;
    int lane = threadIdx.x & 31, wid = threadIdx.x >> 5;

    // last warp computes this block's global offset with parallel loads
    if (wid == 31) {
        int acc = 0;
        for (int b = lane; b < blockIdx.x; b += 32) acc += g_blocksum[b];
        #pragma unroll
        for (int o = 16; o > 0; o >>= 1) acc += __shfl_down_sync(0xFFFFFFFFu, acc, o);
        if (lane == 0) blockoff = acc;
    }

    int inc = v;
    #pragma unroll
    for (int o = 1; o < 32; o <<= 1) {
        int t = __shfl_up_sync(0xFFFFFFFFu, inc, o);
        if (lane >= o) inc += t;
    }
    if (lane == 31) warpsum[wid] = inc;
    __syncthreads();
    if (wid == 0) {
        int orig = warpsum[lane];
        int sc = orig;
        #pragma unroll
        for (int o = 1; o < 32; o <<= 1) {
            int t = __shfl_up_sync(0xFFFFFFFFu, sc, o);
            if (lane >= o) sc += t;
        }
        warpsum[lane] = sc - orig;   // exclusive per-warp offset
    }
    __syncthreads();
    int excl = inc - v + warpsum[wid] + blockoff;
    if (i < n) {
        g_rowstart[i] = excl;
        g_cursor[i]   = excl;
        int od = g_outdeg[i]; if (od < 1) od = 1;
        g_rsout[i] = rsqrtf((float)od);
    }
    if (i == n - 1) g_rowstart[n] = excl + v;
}

// K4: scatter edge srcs into CSR buckets by dst, 2 edges per thread.
__global__ void k_fill(const void* __restrict__ src, const void* __restrict__ dst,
                       int n_edges) {
    int t = blockIdx.x * blockDim.x + threadIdx.x;
    int e0 = t * 2;
    if (e0 >= n_edges) return;
    int is64 = g_is64;
    int s0, s1, d0, d1;
    bool two = (e0 + 1 < n_edges);
    if (is64) {
        if (two) {
            ulonglong2 sv = ((const ulonglong2*)src)[t];
            ulonglong2 dv = ((const ulonglong2*)dst)[t];
            s0 = (int)sv.x; s1 = (int)sv.y; d0 = (int)dv.x; d1 = (int)dv.y;
        } else {
            s0 = (int)((const long long*)src)[e0]; s1 = 0;
            d0 = (int)((const long long*)dst)[e0]; d1 = 0;
        }
    } else {
        if (two) {
            int2 sv = ((const int2*)src)[t];
            int2 dv = ((const int2*)dst)[t];
            s0 = sv.x; s1 = sv.y; d0 = dv.x; d1 = dv.y;
        } else {
            s0 = ((const int*)src)[e0]; s1 = 0;
            d0 = ((const int*)dst)[e0]; d1 = 0;
        }
    }
    int p0 = atomicAdd(&g_cursor[d0], 1);
    g_csr[p0] = s0;
    if (two) {
        int p1 = atomicAdd(&g_cursor[d1], 1);
        g_csr[p1] = s1;
    }
}

// K5: warp-per-node gather, 2-edge unroll for MLP.
__global__ void __launch_bounds__(256) k_gather(const float4* __restrict__ x,
                                                float4* __restrict__ out,
                                                int n_nodes) {
    int w = (blockIdx.x * blockDim.x + threadIdx.x) >> 5;
    if (w >= n_nodes) return;
    int lane = threadIdx.x & 31;
    int beg = g_rowstart[w];
    int end = g_rowstart[w + 1];
    float4 acc = make_float4(0.f, 0.f, 0.f, 0.f);
    int j = beg;
    for (; j + 2 <= end; j += 2) {
        int s0 = g_csr[j];
        int s1 = g_csr[j + 1];
        float c0 = g_rsout[s0];
        float c1 = g_rsout[s1];
        if (lane < DV) {
            float4 v0 = x[s0 * DV + lane];
            float4 v1 = x[s1 * DV + lane];
            acc.x = fmaf(v0.x, c0, acc.x); acc.y = fmaf(v0.y, c0, acc.y);
            acc.z = fmaf(v0.z, c0, acc.z); acc.w = fmaf(v0.w, c0, acc.w);
            acc.x = fmaf(v1.x, c1, acc.x); acc.y = fmaf(v1.y, c1, acc.y);
            acc.z = fmaf(v1.z, c1, acc.z); acc.w = fmaf(v1.w, c1, acc.w);
        }
    }
    if (j < end) {
        int s = g_csr[j];
        float c = g_rsout[s];
        if (lane < DV) {
            float4 v = x[s * DV + lane];
            acc.x = fmaf(v.x, c, acc.x); acc.y = fmaf(v.y, c, acc.y);
            acc.z = fmaf(v.z, c, acc.z); acc.w = fmaf(v.w, c, acc.w);
        }
    }
    int deg = end - beg; if (deg < 1) deg = 1;
    float rsin = rsqrtf((float)deg);
    if (lane < DV) {
        acc.x *= rsin; acc.y *= rsin; acc.z *= rsin; acc.w *= rsin;
        out[w * DV + lane] = acc;
    }
}

extern "C" void kernel_launch(void* const* d_in, const int* in_sizes, int n_in,
                              void* d_out, int out_size) {
    const float* x   = (const float*)d_in[0];
    const void*  src = d_in[1];
    const void*  dst = d_in[2];
    float* out = (float*)d_out;

    int n_nodes = in_sizes[0] / DFEAT;   // 50000
    int n_edges = in_sizes[1];           // 800000

    const int B = 256;
    int nblk_scan = (n_nodes + CHUNK - 1) / CHUNK;   // 49
    int npair = (n_edges + 1) / 2;

    k_init<<<(n_nodes + B - 1) / B, B>>>(n_nodes,
                                         (const unsigned long long*)src, n_edges);
    k_deg<<<(npair + B - 1) / B, B>>>(src, dst, n_edges);
    k_scan_sum<<<nblk_scan, 256>>>(n_nodes);
    k_scan_final<<<nblk_scan, CHUNK>>>(n_nodes, nblk_scan);
    k_fill<<<(npair + B - 1) / B, B>>>(src, dst, n_edges);
    int gather_threads = n_nodes * 32;
    k_gather<<<(gather_threads + B - 1) / B, B>>>((const float4*)x,
                                                  (float4*)out, n_nodes);
}